// round 6
// baseline (speedup 1.0000x reference)
#include <cuda_runtime.h>
#include <cuda_fp16.h>
#include <cstdint>

// Problem constants
#define TN      2000
#define UN      50000
#define TF      16
#define NOUT    52          // 16 static + 36 emb
#define UN_PAD  50048       // 782 * 64
#define KTILES  782
#define KSPLIT  18          // 16 mtiles * 18 = 288 CTAs = one full wave at occ 2
#define MT      128
#define MTILES  16          // 2048 / 128
#define KB8     (UN_PAD / 8)   // 6256 eight-wide k-blocks per row

// Device scratch (no allocations allowed)
__device__ __half g_ubT[64 * UN_PAD];   // U_emb^T fp16: rows 0..35 emb, 36 ones, 37..39 zero pad
__device__ float g_partial[(size_t)2048 * KSPLIT * 40];   // [gm][ks][40]

__device__ __forceinline__ uint32_t sw128(uint32_t off) {
    return off ^ ((off >> 3) & 0x70u);
}
__device__ __forceinline__ uint32_t cvta_sh(const void* p) {
    return (uint32_t)__cvta_generic_to_shared(p);
}
__device__ __forceinline__ void ldsm_x4(uint32_t* r, uint32_t addr) {
    asm volatile("ldmatrix.sync.aligned.m8n8.x4.shared.b16 {%0,%1,%2,%3}, [%4];"
                 : "=r"(r[0]), "=r"(r[1]), "=r"(r[2]), "=r"(r[3]) : "r"(addr));
}
__device__ __forceinline__ void mma16816(float* c, const uint32_t* a, uint32_t b0, uint32_t b1) {
    asm volatile(
        "mma.sync.aligned.m16n8k16.row.col.f32.f16.f16.f32 "
        "{%0,%1,%2,%3}, {%4,%5,%6,%7}, {%8,%9}, {%0,%1,%2,%3};"
        : "+f"(c[0]), "+f"(c[1]), "+f"(c[2]), "+f"(c[3])
        : "r"(a[0]), "r"(a[1]), "r"(a[2]), "r"(a[3]), "r"(b0), "r"(b1));
}

// ---------------------------------------------------------------------------
// Kernel 1: build U_emb^T rows 0..39, row-major work -> coalesced 16B stores.
// One thread per (row, 8-k block): 8 independent gathers + one float4 store.
// ---------------------------------------------------------------------------
__global__ void prep_kernel(const int* __restrict__ Uw,
                            const float* __restrict__ e0, const float* __restrict__ e1,
                            const float* __restrict__ e2, const float* __restrict__ e3,
                            const float* __restrict__ e4, const float* __restrict__ e5) {
    __shared__ int s_is64;
    if (threadIdx.x == 0) {
        // int64 little-endian with small values -> every odd word zero.
        bool b = true;
        for (int j = 1; j < 129; j += 2) b = b && (Uw[j] == 0);
        s_is64 = b ? 1 : 0;
    }
    __syncthreads();
    const bool is64 = (s_is64 != 0);

    int gid = blockIdx.x * 256 + threadIdx.x;
    if (gid >= 40 * KB8) return;
    int row = gid / KB8;
    int kb  = (gid - row * KB8) * 8;

    __half2 h[4];
    if (row < 36) {
        int f = row / 6, d = row - 6 * f;
        const float* tab; int sz;
        switch (f) {
            case 0: tab = e0; sz = 222; break;
            case 1: tab = e1; sz = 27;  break;
            case 2: tab = e2; sz = 373; break;
            case 3: tab = e3; sz = 283; break;
            case 4: tab = e4; sz = 26;  break;
            default: tab = e5; sz = 7;  break;
        }
        float v[8];
#pragma unroll
        for (int j = 0; j < 8; j++) {
            int k = kb + j;
            float val = 0.0f;
            if (k < UN) {
                int elem = k * 6 + f;
                int idx = is64 ? Uw[2 * elem] : Uw[elem];
                idx = max(0, min(sz - 1, idx));
                val = tab[idx * 6 + d];
            }
            v[j] = val;
        }
#pragma unroll
        for (int j = 0; j < 4; j++)
            h[j] = __floats2half2_rn(v[2 * j], v[2 * j + 1]);
    } else if (row == 36) {
        // counts row: 1.0 everywhere (k >= UN harmless, mask A is 0 there)
        __half2 one2 = __floats2half2_rn(1.0f, 1.0f);
#pragma unroll
        for (int j = 0; j < 4; j++) h[j] = one2;
    } else {
        __half2 z2 = __floats2half2_rn(0.0f, 0.0f);
#pragma unroll
        for (int j = 0; j < 4; j++) h[j] = z2;
    }
    *(float4*)(void*)(g_ubT + (size_t)row * UN_PAD + kb) = *(const float4*)(const void*)h;
}

// ---------------------------------------------------------------------------
// Kernel 2: mask[2000,50000] @ U_emb[50000,64-ish] via mma.sync fp16.
// Grid: (16 m-tiles, 18 k-splits) = 288 CTAs = one wave at occ 2.
// Double-buffered smem, ONE __syncthreads per k-tile. B staged 40 rows/tile;
// smem rows 40..47 zeroed once; (wn=1,nj=1) quadrant (cols 48..63) skipped.
// ---------------------------------------------------------------------------
extern __shared__ __align__(16) char dynsmem[];

__global__ __launch_bounds__(256, 2) void gemm_kernel(const int* __restrict__ mask) {
    // layout: A0 [0,16K) A1 [16K,32K) B0 [32K,40K) B1 [40K,48K)
    const int tid  = threadIdx.x;
    const int lane = tid & 31;
    const int wid  = tid >> 5;
    const int wm   = wid & 3;    // 4 warps over M
    const int wn   = wid >> 2;   // 2 warps over N
    const int mtile  = blockIdx.x;
    const int ks     = blockIdx.y;
    const int mbase  = mtile * MT;
    const int ktile0 = ks * 43 + min(ks, 8);
    const int cnt    = 43 + (ks < 8 ? 1 : 0);

    const uint32_t smem_u = cvta_sh(dynsmem);
    const uint32_t shA_u[2] = {smem_u, smem_u + 16384};
    const uint32_t shB_u[2] = {smem_u + 32768, smem_u + 40960};

    // zero B rows 40..47 in both buffers once ([5120,6144): 1KB-block aligned,
    // so the swizzled images of those rows stay inside this range)
    if (tid < 128) {
        int b = tid >> 6, off = (tid & 63) * 16;
        uint32_t a = shB_u[b] + 5120 + off;
        asm volatile("st.shared.v4.b32 [%0], {%1,%1,%1,%1};" :: "r"(a), "r"(0u));
    }

    int4 ra[8];  // next A tile: 128x64 int32 mask, 8 x int4 per thread
    int4 rb[2];  // next B tile rows 0..39: slots 0..319 of int4

    auto load_regs = [&](int kt) {
        const int kb = (ktile0 + kt) * 64;
#pragma unroll
        for (int i = 0; i < 8; i++) {
            int slot = tid + i * 256;
            int row = slot >> 4, c4 = slot & 15;
            int gt = mbase + row, gk = kb + c4 * 4;
            if (gt < TN && gk < UN)
                ra[i] = __ldcs((const int4*)(mask + (size_t)gt * UN + gk));  // evict-first
            else
                ra[i] = make_int4(0, 0, 0, 0);
        }
        {
            int row = tid >> 3, c8 = tid & 7;
            rb[0] = *(const int4*)(const void*)(g_ubT + (size_t)row * UN_PAD + kb + c8 * 8);
        }
        if (tid < 64) {
            int slot = 256 + tid;
            int row = slot >> 3, c8 = slot & 7;
            rb[1] = *(const int4*)(const void*)(g_ubT + (size_t)row * UN_PAD + kb + c8 * 8);
        }
    };

    auto sts_tiles = [&](int buf) {
#pragma unroll
        for (int i = 0; i < 8; i++) {
            int slot = tid + i * 256;
            int row = slot >> 4, c4 = slot & 15;
            // int32 0/1 pair -> packed fp16x2 via integer IMAD (1.0f16 = 0x3C00)
            uint32_t p0 = (uint32_t)ra[i].x * 0x3C00u + (uint32_t)ra[i].y * 0x3C000000u;
            uint32_t p1 = (uint32_t)ra[i].z * 0x3C00u + (uint32_t)ra[i].w * 0x3C000000u;
            uint32_t a = shA_u[buf] + sw128(row * 128 + c4 * 8);
            asm volatile("st.shared.v2.b32 [%0], {%1,%2};" :: "r"(a), "r"(p0), "r"(p1));
        }
        {
            int row = tid >> 3, c8 = tid & 7;
            uint32_t a = shB_u[buf] + sw128(row * 128 + c8 * 16);
            asm volatile("st.shared.v4.b32 [%0], {%1,%2,%3,%4};"
                         :: "r"(a), "r"(rb[0].x), "r"(rb[0].y), "r"(rb[0].z), "r"(rb[0].w));
        }
        if (tid < 64) {
            int slot = 256 + tid;
            int row = slot >> 3, c8 = slot & 7;
            uint32_t a = shB_u[buf] + sw128(row * 128 + c8 * 16);
            asm volatile("st.shared.v4.b32 [%0], {%1,%2,%3,%4};"
                         :: "r"(a), "r"(rb[1].x), "r"(rb[1].y), "r"(rb[1].z), "r"(rb[1].w));
        }
    };

    float acc[2][4][4];
#pragma unroll
    for (int a = 0; a < 2; a++)
#pragma unroll
        for (int b = 0; b < 4; b++)
#pragma unroll
            for (int c = 0; c < 4; c++) acc[a][b][c] = 0.0f;

    load_regs(0);
    sts_tiles(0);
    if (cnt > 1) load_regs(1);
    __syncthreads();

    for (int kt = 0; kt < cnt; kt++) {
        const int cur = kt & 1;
        if (kt + 1 < cnt) sts_tiles(cur ^ 1);   // stage next tile into other buffer
        if (kt + 2 < cnt) load_regs(kt + 2);    // LDGs overlap the MMAs below

        // ---- MMA over 4 k16-steps on buffer `cur` ----
#pragma unroll
        for (int kk = 0; kk < 4; kk++) {
            const int kb2 = kk * 32;  // 16 fp16 = 32 bytes
            uint32_t A[2][4];
#pragma unroll
            for (int mi = 0; mi < 2; mi++) {
                int row = wm * 32 + mi * 16 + (lane & 15);
                ldsm_x4(A[mi], shA_u[cur] + sw128(row * 128 + kb2 + ((lane >> 4) << 4)));
            }
#pragma unroll
            for (int nj = 0; nj < 2; nj++) {
                if (wn == 1 && nj == 1) continue;   // cols 48..63 are all-zero padding
                int nl = wn * 32 + nj * 16 + (lane & 7) + (((lane >> 4) & 1) << 3);
                uint32_t koff = kb2 + ((lane >> 3) & 1) * 16;
                uint32_t Bh[4];
                ldsm_x4(Bh, shB_u[cur] + sw128((uint32_t)nl * 128 + koff));
                mma16816(acc[0][nj * 2 + 0], A[0], Bh[0], Bh[1]);
                mma16816(acc[1][nj * 2 + 0], A[1], Bh[0], Bh[1]);
                mma16816(acc[0][nj * 2 + 1], A[0], Bh[2], Bh[3]);
                mma16816(acc[1][nj * 2 + 1], A[1], Bh[2], Bh[3]);
            }
        }
        __syncthreads();   // next iter's sts may overwrite buffer cur^1's reader state
    }

    // ---- epilogue: exclusive partial slab [gm][ks][40]; only cols < 40 ----
#pragma unroll
    for (int mi = 0; mi < 2; mi++)
#pragma unroll
        for (int nc = 0; nc < 4; nc++) {
            int gn = wn * 32 + nc * 8 + (lane & 3) * 2;
            if (gn >= 40) continue;   // finalize only reads n < 37
            int lm = wm * 32 + mi * 16 + (lane >> 2);
            int gm = mbase + lm;
            float* d0 = &g_partial[((size_t)gm * KSPLIT + ks) * 40 + gn];
            *(float2*)d0 = make_float2(acc[mi][nc][0], acc[mi][nc][1]);
            float* d1 = &g_partial[((size_t)(gm + 8) * KSPLIT + ks) * 40 + gn];
            *(float2*)d1 = make_float2(acc[mi][nc][2], acc[mi][nc][3]);
        }
}

// ---------------------------------------------------------------------------
// Kernel 3: reduce k-splits (now contiguous per team), divide by counts,
// prepend statics.
// ---------------------------------------------------------------------------
__global__ void finalize_kernel(const float* __restrict__ Ts, float* __restrict__ out) {
    int t = blockIdx.x;
    int n = threadIdx.x;  // 64 threads
    __shared__ float sv[40];
    if (n < 37) {
        float s = 0.0f;
#pragma unroll
        for (int ksp = 0; ksp < KSPLIT; ksp++)
            s += g_partial[((size_t)t * KSPLIT + ksp) * 40 + n];
        sv[n] = s;
    }
    __syncthreads();
    if (n < 36) {
        out[(size_t)t * NOUT + TF + n] = sv[n] / sv[36];
    } else if (n < 36 + TF) {
        int i = n - 36;
        out[(size_t)t * NOUT + i] = Ts[(size_t)t * TF + i];
    }
}

// ---------------------------------------------------------------------------
// Inputs (metadata order): T_static f32[2000,16], U_static int (see prep),
// team_user_matrix i32[2000,50000], emb0..emb5 f32. Output f32[2000,52].
// ---------------------------------------------------------------------------
extern "C" void kernel_launch(void* const* d_in, const int* in_sizes, int n_in,
                              void* d_out, int out_size) {
    const float* Ts   = (const float*)d_in[0];
    const int*   Uw   = (const int*)d_in[1];
    const int*   mask = (const int*)d_in[2];
    const float* e0 = (const float*)d_in[3];
    const float* e1 = (const float*)d_in[4];
    const float* e2 = (const float*)d_in[5];
    const float* e3 = (const float*)d_in[6];
    const float* e4 = (const float*)d_in[7];
    const float* e5 = (const float*)d_in[8];
    float* out = (float*)d_out;

    static bool attr_set = false;
    if (!attr_set) {
        cudaFuncSetAttribute(gemm_kernel, cudaFuncAttributeMaxDynamicSharedMemorySize, 49152);
        attr_set = true;
    }

    prep_kernel<<<(40 * KB8 + 255) / 256, 256>>>(Uw, e0, e1, e2, e3, e4, e5);
    dim3 grid(MTILES, KSPLIT);
    gemm_kernel<<<grid, 256, 49152>>>(mask);
    finalize_kernel<<<TN, 64>>>(Ts, out);
}

// round 7
// speedup vs baseline: 1.0776x; 1.0776x over previous
#include <cuda_runtime.h>
#include <cuda_fp16.h>
#include <cstdint>

// Problem constants
#define TN      2000
#define UN      50000
#define TF      16
#define NOUT    52          // 16 static + 36 emb
#define UN_PAD  50048       // 782 * 64
#define KTILES  782
#define KSPLIT  18          // 16 mtiles * 18 = 288 CTAs = one full wave at occ 2
#define MT      128
#define MTILES  16          // 2048 / 128

// Device scratch (no allocations allowed)
__device__ __half g_ubT[64 * UN_PAD];   // U_emb^T fp16: rows 0..35 emb, 36 ones, 37..39 zero pad
__device__ float g_partial[(size_t)2048 * KSPLIT * 40];   // [gm][ks][40]

__device__ __forceinline__ uint32_t sw128(uint32_t off) {
    return off ^ ((off >> 3) & 0x70u);
}
__device__ __forceinline__ uint32_t cvta_sh(const void* p) {
    return (uint32_t)__cvta_generic_to_shared(p);
}
__device__ __forceinline__ void ldsm_x4(uint32_t* r, uint32_t addr) {
    asm volatile("ldmatrix.sync.aligned.m8n8.x4.shared.b16 {%0,%1,%2,%3}, [%4];"
                 : "=r"(r[0]), "=r"(r[1]), "=r"(r[2]), "=r"(r[3]) : "r"(addr));
}
__device__ __forceinline__ void mma16816(float* c, const uint32_t* a, uint32_t b0, uint32_t b1) {
    asm volatile(
        "mma.sync.aligned.m16n8k16.row.col.f32.f16.f16.f32 "
        "{%0,%1,%2,%3}, {%4,%5,%6,%7}, {%8,%9}, {%0,%1,%2,%3};"
        : "+f"(c[0]), "+f"(c[1]), "+f"(c[2]), "+f"(c[3])
        : "r"(a[0]), "r"(a[1]), "r"(a[2]), "r"(a[3]), "r"(b0), "r"(b1));
}

// ---------------------------------------------------------------------------
// Kernel 1 (v3): one thread per user gathers its 36 values (each index read
// ONCE, table gathers L1-resident), transposes through shared, then emits
// fully-coalesced row-major stores. Stage padded to 264 to dodge conflicts.
// ---------------------------------------------------------------------------
__global__ void prep_kernel(const int* __restrict__ Uw,
                            const float* __restrict__ e0, const float* __restrict__ e1,
                            const float* __restrict__ e2, const float* __restrict__ e3,
                            const float* __restrict__ e4, const float* __restrict__ e5) {
    __shared__ __half stage[40][264];   // 21.1 KB
    __shared__ int s_is64;
    if (threadIdx.x == 0) {
        // int64 little-endian with small values -> every odd word zero.
        bool b = true;
        for (int j = 1; j < 129; j += 2) b = b && (Uw[j] == 0);
        s_is64 = b ? 1 : 0;
    }
    __syncthreads();
    const bool is64 = (s_is64 != 0);

    const int u  = threadIdx.x;          // user slot within CTA
    const int k0 = blockIdx.x * 256;
    const int k  = k0 + u;

    const int sizes[6] = {222, 27, 373, 283, 26, 7};
    const float* tabs[6] = {e0, e1, e2, e3, e4, e5};

    float v[36];
#pragma unroll
    for (int i = 0; i < 36; i++) v[i] = 0.0f;
    if (k < UN) {
        int idxs[6];
#pragma unroll
        for (int f = 0; f < 6; f++) {
            int elem = k * 6 + f;
            int idx = is64 ? Uw[2 * elem] : Uw[elem];
            idxs[f] = max(0, min(sizes[f] - 1, idx));
        }
#pragma unroll
        for (int f = 0; f < 6; f++) {
            const float* t = tabs[f] + (size_t)idxs[f] * 6;
#pragma unroll
            for (int d = 0; d < 6; d++) v[f * 6 + d] = t[d];
        }
    }
#pragma unroll
    for (int n = 0; n < 36; n++) stage[n][u] = __float2half(v[n]);
    stage[36][u] = __float2half(1.0f);     // counts row
    stage[37][u] = __float2half(0.0f);
    stage[38][u] = __float2half(0.0f);
    stage[39][u] = __float2half(0.0f);
    __syncthreads();

    // coalesced emit: 40 rows x 128 uint32 (256 users) = 5120 words, 20 iters
#pragma unroll
    for (int i = 0; i < 20; i++) {
        int idx = threadIdx.x + i * 256;
        int row = idx >> 7, c = idx & 127;
        uint32_t val = *(const uint32_t*)(const void*)&stage[row][2 * c];
        *(uint32_t*)(void*)(g_ubT + (size_t)row * UN_PAD + k0 + 2 * c) = val;
    }
}

// ---------------------------------------------------------------------------
// Kernel 2: mask[2000,50000] @ U_emb[50000,64-ish] via mma.sync fp16.
// Grid: (16 m-tiles, 18 k-splits) = 288 CTAs = one wave at occ 2.
// Double-buffered smem, ONE __syncthreads per k-tile. B staged 40 rows/tile;
// smem rows 40..47 zeroed once; (wn=1,nj=1) quadrant (cols 48..63) skipped.
// ---------------------------------------------------------------------------
extern __shared__ __align__(16) char dynsmem[];

__global__ __launch_bounds__(256, 2) void gemm_kernel(const int* __restrict__ mask) {
    // layout: A0 [0,16K) A1 [16K,32K) B0 [32K,40K) B1 [40K,48K)
    const int tid  = threadIdx.x;
    const int lane = tid & 31;
    const int wid  = tid >> 5;
    const int wm   = wid & 3;    // 4 warps over M
    const int wn   = wid >> 2;   // 2 warps over N
    const int mtile  = blockIdx.x;
    const int ks     = blockIdx.y;
    const int mbase  = mtile * MT;
    const int ktile0 = ks * 43 + min(ks, 8);
    const int cnt    = 43 + (ks < 8 ? 1 : 0);

    const uint32_t smem_u = cvta_sh(dynsmem);
    const uint32_t shA_u[2] = {smem_u, smem_u + 16384};
    const uint32_t shB_u[2] = {smem_u + 32768, smem_u + 40960};

    // zero B rows 40..47 in both buffers once ([5120,6144): 1KB-block aligned,
    // so the swizzled images of those rows stay inside this range)
    if (tid < 128) {
        int b = tid >> 6, off = (tid & 63) * 16;
        uint32_t a = shB_u[b] + 5120 + off;
        asm volatile("st.shared.v4.b32 [%0], {%1,%1,%1,%1};" :: "r"(a), "r"(0u));
    }

    int4 ra[8];  // next A tile: 128x64 int32 mask, 8 x int4 per thread
    int4 rb[2];  // next B tile rows 0..39: slots 0..319 of int4

    auto load_regs = [&](int kt) {
        const int kb = (ktile0 + kt) * 64;
#pragma unroll
        for (int i = 0; i < 8; i++) {
            int slot = tid + i * 256;
            int row = slot >> 4, c4 = slot & 15;
            int gt = mbase + row, gk = kb + c4 * 4;
            if (gt < TN && gk < UN)
                ra[i] = __ldcs((const int4*)(mask + (size_t)gt * UN + gk));  // evict-first
            else
                ra[i] = make_int4(0, 0, 0, 0);
        }
        {
            int row = tid >> 3, c8 = tid & 7;
            rb[0] = *(const int4*)(const void*)(g_ubT + (size_t)row * UN_PAD + kb + c8 * 8);
        }
        if (tid < 64) {
            int slot = 256 + tid;
            int row = slot >> 3, c8 = slot & 7;
            rb[1] = *(const int4*)(const void*)(g_ubT + (size_t)row * UN_PAD + kb + c8 * 8);
        }
    };

    auto sts_tiles = [&](int buf) {
#pragma unroll
        for (int i = 0; i < 8; i++) {
            int slot = tid + i * 256;
            int row = slot >> 4, c4 = slot & 15;
            // int32 0/1 pair -> packed fp16x2 via integer IMAD (1.0f16 = 0x3C00)
            uint32_t p0 = (uint32_t)ra[i].x * 0x3C00u + (uint32_t)ra[i].y * 0x3C000000u;
            uint32_t p1 = (uint32_t)ra[i].z * 0x3C00u + (uint32_t)ra[i].w * 0x3C000000u;
            uint32_t a = shA_u[buf] + sw128(row * 128 + c4 * 8);
            asm volatile("st.shared.v2.b32 [%0], {%1,%2};" :: "r"(a), "r"(p0), "r"(p1));
        }
        {
            int row = tid >> 3, c8 = tid & 7;
            uint32_t a = shB_u[buf] + sw128(row * 128 + c8 * 16);
            asm volatile("st.shared.v4.b32 [%0], {%1,%2,%3,%4};"
                         :: "r"(a), "r"(rb[0].x), "r"(rb[0].y), "r"(rb[0].z), "r"(rb[0].w));
        }
        if (tid < 64) {
            int slot = 256 + tid;
            int row = slot >> 3, c8 = slot & 7;
            uint32_t a = shB_u[buf] + sw128(row * 128 + c8 * 16);
            asm volatile("st.shared.v4.b32 [%0], {%1,%2,%3,%4};"
                         :: "r"(a), "r"(rb[1].x), "r"(rb[1].y), "r"(rb[1].z), "r"(rb[1].w));
        }
    };

    float acc[2][4][4];
#pragma unroll
    for (int a = 0; a < 2; a++)
#pragma unroll
        for (int b = 0; b < 4; b++)
#pragma unroll
            for (int c = 0; c < 4; c++) acc[a][b][c] = 0.0f;

    load_regs(0);
    sts_tiles(0);
    if (cnt > 1) load_regs(1);
    __syncthreads();

    for (int kt = 0; kt < cnt; kt++) {
        const int cur = kt & 1;
        if (kt + 1 < cnt) sts_tiles(cur ^ 1);   // stage next tile into other buffer
        if (kt + 2 < cnt) load_regs(kt + 2);    // LDGs overlap the MMAs below

        // ---- MMA over 4 k16-steps on buffer `cur` ----
#pragma unroll
        for (int kk = 0; kk < 4; kk++) {
            const int kb2 = kk * 32;  // 16 fp16 = 32 bytes
            uint32_t A[2][4];
#pragma unroll
            for (int mi = 0; mi < 2; mi++) {
                int row = wm * 32 + mi * 16 + (lane & 15);
                ldsm_x4(A[mi], shA_u[cur] + sw128(row * 128 + kb2 + ((lane >> 4) << 4)));
            }
#pragma unroll
            for (int nj = 0; nj < 2; nj++) {
                if (wn == 1 && nj == 1) continue;   // cols 48..63 are all-zero padding
                int nl = wn * 32 + nj * 16 + (lane & 7) + (((lane >> 4) & 1) << 3);
                uint32_t koff = kb2 + ((lane >> 3) & 1) * 16;
                uint32_t Bh[4];
                ldsm_x4(Bh, shB_u[cur] + sw128((uint32_t)nl * 128 + koff));
                mma16816(acc[0][nj * 2 + 0], A[0], Bh[0], Bh[1]);
                mma16816(acc[1][nj * 2 + 0], A[1], Bh[0], Bh[1]);
                mma16816(acc[0][nj * 2 + 1], A[0], Bh[2], Bh[3]);
                mma16816(acc[1][nj * 2 + 1], A[1], Bh[2], Bh[3]);
            }
        }
        __syncthreads();   // next iter's sts may overwrite buffer cur^1's reader state
    }

    // ---- epilogue: exclusive partial slab [gm][ks][40]; only cols < 40 ----
#pragma unroll
    for (int mi = 0; mi < 2; mi++)
#pragma unroll
        for (int nc = 0; nc < 4; nc++) {
            int gn = wn * 32 + nc * 8 + (lane & 3) * 2;
            if (gn >= 40) continue;   // finalize only reads n < 37
            int lm = wm * 32 + mi * 16 + (lane >> 2);
            int gm = mbase + lm;
            float* d0 = &g_partial[((size_t)gm * KSPLIT + ks) * 40 + gn];
            *(float2*)d0 = make_float2(acc[mi][nc][0], acc[mi][nc][1]);
            float* d1 = &g_partial[((size_t)(gm + 8) * KSPLIT + ks) * 40 + gn];
            *(float2*)d1 = make_float2(acc[mi][nc][2], acc[mi][nc][3]);
        }
}

// ---------------------------------------------------------------------------
// Kernel 3: reduce k-splits (contiguous per team), divide by counts,
// prepend statics.
// ---------------------------------------------------------------------------
__global__ void finalize_kernel(const float* __restrict__ Ts, float* __restrict__ out) {
    int t = blockIdx.x;
    int n = threadIdx.x;  // 64 threads
    __shared__ float sv[40];
    if (n < 37) {
        float s = 0.0f;
#pragma unroll
        for (int ksp = 0; ksp < KSPLIT; ksp++)
            s += g_partial[((size_t)t * KSPLIT + ksp) * 40 + n];
        sv[n] = s;
    }
    __syncthreads();
    if (n < 36) {
        out[(size_t)t * NOUT + TF + n] = sv[n] / sv[36];
    } else if (n < 36 + TF) {
        int i = n - 36;
        out[(size_t)t * NOUT + i] = Ts[(size_t)t * TF + i];
    }
}

// ---------------------------------------------------------------------------
// Inputs (metadata order): T_static f32[2000,16], U_static int (see prep),
// team_user_matrix i32[2000,50000], emb0..emb5 f32. Output f32[2000,52].
// ---------------------------------------------------------------------------
extern "C" void kernel_launch(void* const* d_in, const int* in_sizes, int n_in,
                              void* d_out, int out_size) {
    const float* Ts   = (const float*)d_in[0];
    const int*   Uw   = (const int*)d_in[1];
    const int*   mask = (const int*)d_in[2];
    const float* e0 = (const float*)d_in[3];
    const float* e1 = (const float*)d_in[4];
    const float* e2 = (const float*)d_in[5];
    const float* e3 = (const float*)d_in[6];
    const float* e4 = (const float*)d_in[7];
    const float* e5 = (const float*)d_in[8];
    float* out = (float*)d_out;

    static bool attr_set = false;
    if (!attr_set) {
        cudaFuncSetAttribute(gemm_kernel, cudaFuncAttributeMaxDynamicSharedMemorySize, 49152);
        attr_set = true;
    }

    prep_kernel<<<(UN_PAD + 255) / 256, 256>>>(Uw, e0, e1, e2, e3, e4, e5);
    dim3 grid(MTILES, KSPLIT);
    gemm_kernel<<<grid, 256, 49152>>>(mask);
    finalize_kernel<<<TN, 64>>>(Ts, out);
}